// round 3
// baseline (speedup 1.0000x reference)
#include <cuda_runtime.h>
#include <math.h>

#define N_NODES 40000
#define N_EDGES 640000
#define IN_DIM  512
#define HID_DIM 128
#define OUT_DIM 40

// Scratch (allocation-free rule: __device__ globals)
__device__ float g_y[(size_t)N_NODES * HID_DIM];   // x @ W1
__device__ float g_h[(size_t)N_NODES * HID_DIM];   // spmm1 output (pre-bias/relu)
__device__ float g_g[(size_t)N_NODES * OUT_DIM];   // relu(h+b1) @ W2

// ---------------------------------------------------------------------------
// Zero init: g_h and d_out (atomic accumulation targets)
// ---------------------------------------------------------------------------
__global__ __launch_bounds__(256) void zero_kernel(float* __restrict__ out) {
    int i = blockIdx.x * blockDim.x + threadIdx.x;
    if (i < N_NODES * HID_DIM) g_h[i] = 0.0f;
    if (i < N_NODES * OUT_DIM) out[i] = 0.0f;
}

// ---------------------------------------------------------------------------
// GEMM1: Y[M,128] = X[M,512] @ W1[512,128]   (fp32, 128x128x8 tile, 8x8/thread)
// ---------------------------------------------------------------------------
__global__ __launch_bounds__(256) void gemm1_kernel(const float* __restrict__ A,
                                                    const float* __restrict__ W) {
    __shared__ float As[8][132];   // [k][m], padded to dodge bank conflicts
    __shared__ float Bs[8][128];   // [k][n]

    const int tid = threadIdx.x;
    const int block_row = blockIdx.x * 128;
    const int tx = tid & 15;    // n-tile
    const int ty = tid >> 4;    // m-tile

    float acc[8][8];
#pragma unroll
    for (int i = 0; i < 8; i++)
#pragma unroll
        for (int j = 0; j < 8; j++) acc[i][j] = 0.0f;

    const int a_row = tid >> 1;          // 0..127
    const int a_col = (tid & 1) * 4;     // 0 or 4
    const int b_row = tid >> 5;          // 0..7
    const int b_col = (tid & 31) * 4;

    const int gr = block_row + a_row;
    const bool a_ok = (gr < N_NODES);
    const float* Aptr = A + (size_t)(a_ok ? gr : 0) * IN_DIM + a_col;

    for (int k0 = 0; k0 < IN_DIM; k0 += 8) {
        float4 av = a_ok ? *(const float4*)(Aptr + k0) : make_float4(0.f, 0.f, 0.f, 0.f);
        float4 bv = *(const float4*)(W + (size_t)(k0 + b_row) * HID_DIM + b_col);
        As[a_col + 0][a_row] = av.x;
        As[a_col + 1][a_row] = av.y;
        As[a_col + 2][a_row] = av.z;
        As[a_col + 3][a_row] = av.w;
        *(float4*)&Bs[b_row][b_col] = bv;
        __syncthreads();
#pragma unroll
        for (int k = 0; k < 8; k++) {
            float ar[8], br[8];
#pragma unroll
            for (int i = 0; i < 8; i++) ar[i] = As[k][ty * 8 + i];
#pragma unroll
            for (int j = 0; j < 8; j++) br[j] = Bs[k][tx * 8 + j];
#pragma unroll
            for (int i = 0; i < 8; i++)
#pragma unroll
                for (int j = 0; j < 8; j++) acc[i][j] = fmaf(ar[i], br[j], acc[i][j]);
        }
        __syncthreads();
    }

#pragma unroll
    for (int i = 0; i < 8; i++) {
        int r = block_row + ty * 8 + i;
        if (r < N_NODES) {
#pragma unroll
            for (int j = 0; j < 8; j += 4) {
                float4 v = make_float4(acc[i][j], acc[i][j + 1], acc[i][j + 2], acc[i][j + 3]);
                *(float4*)(g_y + (size_t)r * HID_DIM + tx * 8 + j) = v;
            }
        }
    }
}

// ---------------------------------------------------------------------------
// SpMM1: g_h[row] += val * g_y[col]   (warp per edge, float4 gather, 4 atomics)
// ---------------------------------------------------------------------------
__global__ __launch_bounds__(256) void spmm1_kernel(const int* __restrict__ erow,
                                                    const int* __restrict__ ecol,
                                                    const float* __restrict__ eval) {
    int e = (blockIdx.x * blockDim.x + threadIdx.x) >> 5;
    if (e >= N_EDGES) return;
    const int lane = threadIdx.x & 31;
    // issue all three edge loads before any use (MLP)
    const int   c = __ldg(ecol + e);
    const int   r = __ldg(erow + e);
    const float v = __ldg(eval + e);
    float4 m = *(const float4*)(g_y + (size_t)c * HID_DIM + lane * 4);
    float* dst = g_h + (size_t)r * HID_DIM + lane * 4;
    atomicAdd(dst + 0, v * m.x);
    atomicAdd(dst + 1, v * m.y);
    atomicAdd(dst + 2, v * m.z);
    atomicAdd(dst + 3, v * m.w);
}

// ---------------------------------------------------------------------------
// GEMM2: g_g[r, c] = sum_k relu(g_h[r,k] + b1[k]) * W2[k,c]
// block = (40, 8): 8 rows per block, thread per output element
// ---------------------------------------------------------------------------
__global__ __launch_bounds__(320) void gemm2_kernel(const float* __restrict__ b1,
                                                    const float* __restrict__ W2) {
    __shared__ float W2s[HID_DIM][OUT_DIM];
    __shared__ float hs[8][HID_DIM];
    const int tid = threadIdx.y * OUT_DIM + threadIdx.x;

    for (int i = tid; i < HID_DIM * OUT_DIM; i += 320)
        W2s[i / OUT_DIM][i % OUT_DIM] = W2[i];

    const int row0 = blockIdx.x * 8;
    for (int i = tid; i < 8 * HID_DIM; i += 320) {
        int rr = i >> 7, k = i & 127;
        int r = row0 + rr;
        float val = (r < N_NODES) ? (g_h[(size_t)r * HID_DIM + k] + b1[k]) : 0.0f;
        hs[rr][k] = fmaxf(val, 0.0f);
    }
    __syncthreads();

    const int r = row0 + threadIdx.y;
    if (r >= N_NODES) return;
    float acc = 0.0f;
#pragma unroll
    for (int k = 0; k < HID_DIM; k++)
        acc = fmaf(hs[threadIdx.y][k], W2s[k][threadIdx.x], acc);
    g_g[(size_t)r * OUT_DIM + threadIdx.x] = acc;
}

// ---------------------------------------------------------------------------
// SpMM2: out[row] += val * g_g[col]   (warp per edge, 40 cols)
// lanes 0..39 handle one column; lanes 0..7 also handle cols 32..39
// ---------------------------------------------------------------------------
__global__ __launch_bounds__(256) void spmm2_kernel(const int* __restrict__ erow,
                                                    const int* __restrict__ ecol,
                                                    const float* __restrict__ eval,
                                                    float* __restrict__ out) {
    int e = (blockIdx.x * blockDim.x + threadIdx.x) >> 5;
    if (e >= N_EDGES) return;
    const int lane = threadIdx.x & 31;
    const int   c = __ldg(ecol + e);
    const int   r = __ldg(erow + e);
    const float v = __ldg(eval + e);
    const float* src = g_g + (size_t)c * OUT_DIM;
    float* dst = out + (size_t)r * OUT_DIM;
    float m0 = src[lane];
    float m1 = (lane < OUT_DIM - 32) ? src[lane + 32] : 0.0f;
    atomicAdd(dst + lane, v * m0);
    if (lane < OUT_DIM - 32) atomicAdd(dst + lane + 32, v * m1);
}

// ---------------------------------------------------------------------------
// log_softmax (+ b2) per row, warp per row, in-place on out
// ---------------------------------------------------------------------------
__global__ __launch_bounds__(256) void logsoftmax_kernel(float* __restrict__ out,
                                                         const float* __restrict__ b2) {
    int w = (blockIdx.x * blockDim.x + threadIdx.x) >> 5;
    if (w >= N_NODES) return;
    int lane = threadIdx.x & 31;
    float* row = out + (size_t)w * OUT_DIM;

    float v0 = -1e30f, v1 = -1e30f;
    if (lane < OUT_DIM) v0 = row[lane] + b2[lane];
    if (lane + 32 < OUT_DIM) v1 = row[lane + 32] + b2[lane + 32];

    float m = fmaxf(v0, v1);
#pragma unroll
    for (int off = 16; off > 0; off >>= 1)
        m = fmaxf(m, __shfl_xor_sync(0xFFFFFFFF, m, off));

    float s = 0.0f;
    if (lane < OUT_DIM) s += expf(v0 - m);
    if (lane + 32 < OUT_DIM) s += expf(v1 - m);
#pragma unroll
    for (int off = 16; off > 0; off >>= 1)
        s += __shfl_xor_sync(0xFFFFFFFF, s, off);

    float lse = logf(s) + m;
    if (lane < OUT_DIM) row[lane] = v0 - lse;
    if (lane + 32 < OUT_DIM) row[lane + 32] = v1 - lse;
}

// ---------------------------------------------------------------------------
extern "C" void kernel_launch(void* const* d_in, const int* in_sizes, int n_in,
                              void* d_out, int out_size) {
    const float* x  = (const float*)d_in[0];
    const int*   er = (const int*)  d_in[1];
    const int*   ec = (const int*)  d_in[2];
    const float* ev = (const float*)d_in[3];
    const float* W1 = (const float*)d_in[4];
    const float* b1 = (const float*)d_in[5];
    const float* W2 = (const float*)d_in[6];
    const float* b2 = (const float*)d_in[7];
    float* out = (float*)d_out;

    (void)in_sizes; (void)n_in; (void)out_size;

    // 1. zero accumulation buffers
    zero_kernel<<<(N_NODES * HID_DIM + 255) / 256, 256>>>(out);

    // 2. y = x @ W1
    gemm1_kernel<<<(N_NODES + 127) / 128, 256>>>(x, W1);

    // 3. h = A @ y (atomic scatter)
    spmm1_kernel<<<(N_EDGES * 32 + 255) / 256, 256>>>(er, ec, ev);

    // 4. g = relu(h + b1) @ W2
    gemm2_kernel<<<(N_NODES + 7) / 8, dim3(OUT_DIM, 8)>>>(b1, W2);

    // 5. o = A @ g (atomic scatter into out)
    spmm2_kernel<<<(N_EDGES * 32 + 255) / 256, 256>>>(er, ec, ev, out);

    // 6. out = log_softmax(o + b2)
    logsoftmax_kernel<<<(N_NODES * 32 + 255) / 256, 256>>>(out, b2);
}

// round 9
// speedup vs baseline: 1.5175x; 1.5175x over previous
#include <cuda_runtime.h>
#include <math.h>

#define N_NODES 40000
#define N_EDGES 640000
#define IN_DIM  512
#define HID_DIM 128
#define OUT_DIM 40

// ---------------------------------------------------------------------------
// Scratch (__device__ globals; allocation-free rule)
// ---------------------------------------------------------------------------
__device__ float g_y[(size_t)N_NODES * HID_DIM];   // x @ W1
__device__ float g_h[(size_t)N_NODES * HID_DIM];   // relu(spmm1 + b1)
__device__ float g_g[(size_t)N_NODES * OUT_DIM];   // g_h @ W2
__device__ int   g_cnt[N_NODES];                   // histogram / running offsets
__device__ int   g_rowptr[N_NODES + 1];            // CSR row pointers
__device__ int   g_scol[N_EDGES];                  // edge cols sorted by row
__device__ float g_sval[N_EDGES];                  // edge vals sorted by row

// ---------------------------------------------------------------------------
// CSR build: zero -> count -> scan -> scatter
// ---------------------------------------------------------------------------
__global__ __launch_bounds__(256) void csr_zero_kernel() {
    int i = blockIdx.x * blockDim.x + threadIdx.x;
    if (i < N_NODES) g_cnt[i] = 0;
}

__global__ __launch_bounds__(256) void csr_count_kernel(const int* __restrict__ erow) {
    int e = blockIdx.x * blockDim.x + threadIdx.x;
    if (e < N_EDGES) atomicAdd(&g_cnt[erow[e]], 1);
}

// single-block exclusive scan over g_cnt -> g_rowptr (and g_cnt = running offsets)
__global__ __launch_bounds__(1024) void csr_scan_kernel() {
    __shared__ int warp_sums[32];
    __shared__ int s_carry;
    const int tid = threadIdx.x;
    const int lane = tid & 31;
    const int wid = tid >> 5;
    if (tid == 0) s_carry = 0;
    __syncthreads();

    for (int base = 0; base < ((N_NODES + 1024) / 1024) * 1024; base += 1024) {
        int idx = base + tid;
        int v = (idx < N_NODES) ? g_cnt[idx] : 0;
        int x = v;
#pragma unroll
        for (int o = 1; o < 32; o <<= 1) {
            int t = __shfl_up_sync(0xFFFFFFFF, x, o);
            if (lane >= o) x += t;
        }
        if (lane == 31) warp_sums[wid] = x;
        __syncthreads();
        if (wid == 0) {
            int w = warp_sums[lane];
#pragma unroll
            for (int o = 1; o < 32; o <<= 1) {
                int t = __shfl_up_sync(0xFFFFFFFF, w, o);
                if (lane >= o) w += t;
            }
            warp_sums[lane] = w;
        }
        __syncthreads();
        int carry = s_carry;
        int excl = x - v + (wid > 0 ? warp_sums[wid - 1] : 0) + carry;
        if (idx <= N_NODES) {
            g_rowptr[idx] = excl;
            if (idx < N_NODES) g_cnt[idx] = excl;
        }
        __syncthreads();
        if (tid == 0) s_carry = carry + warp_sums[31];
        __syncthreads();
    }
}

__global__ __launch_bounds__(256) void csr_scatter_kernel(const int* __restrict__ erow,
                                                          const int* __restrict__ ecol,
                                                          const float* __restrict__ eval) {
    int e = blockIdx.x * blockDim.x + threadIdx.x;
    if (e >= N_EDGES) return;
    int r = erow[e];
    int pos = atomicAdd(&g_cnt[r], 1);
    g_scol[pos] = ecol[e];
    g_sval[pos] = eval[e];
}

// ---------------------------------------------------------------------------
// GEMM1: Y[M,128] = X[M,512] @ W1[512,128]   (fp32, 128x128x8 tile, 8x8/thread)
// ---------------------------------------------------------------------------
__global__ __launch_bounds__(256) void gemm1_kernel(const float* __restrict__ A,
                                                    const float* __restrict__ W) {
    __shared__ float As[8][132];
    __shared__ float Bs[8][128];

    const int tid = threadIdx.x;
    const int block_row = blockIdx.x * 128;
    const int tx = tid & 15;
    const int ty = tid >> 4;

    float acc[8][8];
#pragma unroll
    for (int i = 0; i < 8; i++)
#pragma unroll
        for (int j = 0; j < 8; j++) acc[i][j] = 0.0f;

    const int a_row = tid >> 1;
    const int a_col = (tid & 1) * 4;
    const int b_row = tid >> 5;
    const int b_col = (tid & 31) * 4;

    const int gr = block_row + a_row;
    const bool a_ok = (gr < N_NODES);
    const float* Aptr = A + (size_t)(a_ok ? gr : 0) * IN_DIM + a_col;

    for (int k0 = 0; k0 < IN_DIM; k0 += 8) {
        float4 av = a_ok ? *(const float4*)(Aptr + k0) : make_float4(0.f, 0.f, 0.f, 0.f);
        float4 bv = *(const float4*)(W + (size_t)(k0 + b_row) * HID_DIM + b_col);
        As[a_col + 0][a_row] = av.x;
        As[a_col + 1][a_row] = av.y;
        As[a_col + 2][a_row] = av.z;
        As[a_col + 3][a_row] = av.w;
        *(float4*)&Bs[b_row][b_col] = bv;
        __syncthreads();
#pragma unroll
        for (int k = 0; k < 8; k++) {
            float ar[8], br[8];
#pragma unroll
            for (int i = 0; i < 8; i++) ar[i] = As[k][ty * 8 + i];
#pragma unroll
            for (int j = 0; j < 8; j++) br[j] = Bs[k][tx * 8 + j];
#pragma unroll
            for (int i = 0; i < 8; i++)
#pragma unroll
                for (int j = 0; j < 8; j++) acc[i][j] = fmaf(ar[i], br[j], acc[i][j]);
        }
        __syncthreads();
    }

#pragma unroll
    for (int i = 0; i < 8; i++) {
        int r = block_row + ty * 8 + i;
        if (r < N_NODES) {
#pragma unroll
            for (int j = 0; j < 8; j += 4) {
                float4 v = make_float4(acc[i][j], acc[i][j + 1], acc[i][j + 2], acc[i][j + 3]);
                *(float4*)(g_y + (size_t)r * HID_DIM + tx * 8 + j) = v;
            }
        }
    }
}

// ---------------------------------------------------------------------------
// SpMM1 gather: g_h[row] = relu( sum_e val*g_y[col] + b1 )   (warp per row)
// 4-edge unroll: front-batch 4 (col,val) loads, then 4 independent float4
// gathers in flight (MLP~4-8), then the FMA chain.
// ---------------------------------------------------------------------------
__global__ __launch_bounds__(256) void spmm1_gather_kernel(const float* __restrict__ b1) {
    const int row = blockIdx.x * 8 + (threadIdx.x >> 5);   // 5000 blocks * 8 warps
    const int lane = threadIdx.x & 31;
    const int start = g_rowptr[row];
    const int end = g_rowptr[row + 1];

    float4 acc = make_float4(0.f, 0.f, 0.f, 0.f);
    int i = start;
    for (; i + 4 <= end; i += 4) {
        int c0 = g_scol[i];
        int c1 = g_scol[i + 1];
        int c2 = g_scol[i + 2];
        int c3 = g_scol[i + 3];
        float v0 = g_sval[i];
        float v1 = g_sval[i + 1];
        float v2 = g_sval[i + 2];
        float v3 = g_sval[i + 3];
        float4 m0 = *(const float4*)(g_y + (size_t)c0 * HID_DIM + lane * 4);
        float4 m1 = *(const float4*)(g_y + (size_t)c1 * HID_DIM + lane * 4);
        float4 m2 = *(const float4*)(g_y + (size_t)c2 * HID_DIM + lane * 4);
        float4 m3 = *(const float4*)(g_y + (size_t)c3 * HID_DIM + lane * 4);
        acc.x = fmaf(v0, m0.x, acc.x); acc.y = fmaf(v0, m0.y, acc.y);
        acc.z = fmaf(v0, m0.z, acc.z); acc.w = fmaf(v0, m0.w, acc.w);
        acc.x = fmaf(v1, m1.x, acc.x); acc.y = fmaf(v1, m1.y, acc.y);
        acc.z = fmaf(v1, m1.z, acc.z); acc.w = fmaf(v1, m1.w, acc.w);
        acc.x = fmaf(v2, m2.x, acc.x); acc.y = fmaf(v2, m2.y, acc.y);
        acc.z = fmaf(v2, m2.z, acc.z); acc.w = fmaf(v2, m2.w, acc.w);
        acc.x = fmaf(v3, m3.x, acc.x); acc.y = fmaf(v3, m3.y, acc.y);
        acc.z = fmaf(v3, m3.z, acc.z); acc.w = fmaf(v3, m3.w, acc.w);
    }
    for (; i < end; i++) {
        int c0 = g_scol[i];
        float v0 = g_sval[i];
        float4 m0 = *(const float4*)(g_y + (size_t)c0 * HID_DIM + lane * 4);
        acc.x = fmaf(v0, m0.x, acc.x); acc.y = fmaf(v0, m0.y, acc.y);
        acc.z = fmaf(v0, m0.z, acc.z); acc.w = fmaf(v0, m0.w, acc.w);
    }

    float4 b = *(const float4*)(b1 + lane * 4);
    float4 r;
    r.x = fmaxf(acc.x + b.x, 0.f);
    r.y = fmaxf(acc.y + b.y, 0.f);
    r.z = fmaxf(acc.z + b.z, 0.f);
    r.w = fmaxf(acc.w + b.w, 0.f);
    *(float4*)(g_h + (size_t)row * HID_DIM + lane * 4) = r;
}

// ---------------------------------------------------------------------------
// GEMM2: g_g[32 rows x 40 cols per block] = g_h @ W2
// thread tile 4 rows x 2 cols; block (20,8) = 160 threads; 1250 blocks
// ---------------------------------------------------------------------------
__global__ __launch_bounds__(160) void gemm2_kernel(const float* __restrict__ W2) {
    __shared__ float hs[32][132];            // padded rows
    __shared__ float W2s[HID_DIM][OUT_DIM];  // 20480 B

    const int tid = threadIdx.y * 20 + threadIdx.x;
    const int tx = threadIdx.x;   // 0..19  (col pair)
    const int ty = threadIdx.y;   // 0..7   (row quad)
    const int row0 = blockIdx.x * 32;

    for (int i = tid; i < HID_DIM * OUT_DIM; i += 160)
        ((float*)W2s)[i] = W2[i];

    for (int i = tid; i < 32 * (HID_DIM / 4); i += 160) {
        int rr = i >> 5;
        int c4 = i & 31;
        float4 v = *(const float4*)(g_h + (size_t)(row0 + rr) * HID_DIM + c4 * 4);
        *(float4*)&hs[rr][c4 * 4] = v;
    }
    __syncthreads();

    float acc[4][2];
#pragma unroll
    for (int i = 0; i < 4; i++) { acc[i][0] = 0.f; acc[i][1] = 0.f; }

#pragma unroll 4
    for (int k = 0; k < HID_DIM; k++) {
        float w0 = W2s[k][tx * 2 + 0];
        float w1 = W2s[k][tx * 2 + 1];
        float hr[4];
#pragma unroll
        for (int i = 0; i < 4; i++) hr[i] = hs[ty * 4 + i][k];
#pragma unroll
        for (int i = 0; i < 4; i++) {
            acc[i][0] = fmaf(hr[i], w0, acc[i][0]);
            acc[i][1] = fmaf(hr[i], w1, acc[i][1]);
        }
    }

#pragma unroll
    for (int i = 0; i < 4; i++) {
        int r = row0 + ty * 4 + i;
        float2 v = make_float2(acc[i][0], acc[i][1]);
        *(float2*)(g_g + (size_t)r * OUT_DIM + tx * 2) = v;
    }
}

// ---------------------------------------------------------------------------
// SpMM2 + bias + log_softmax fused: warp per row
// lane covers col = lane (and col = 32+lane for lane<8)
// ---------------------------------------------------------------------------
__global__ __launch_bounds__(256) void spmm2_softmax_kernel(const float* __restrict__ b2,
                                                            float* __restrict__ out) {
    const int row = blockIdx.x * 8 + (threadIdx.x >> 5);
    const int lane = threadIdx.x & 31;
    const int start = g_rowptr[row];
    const int end = g_rowptr[row + 1];
    const bool hi = lane < (OUT_DIM - 32);

    float a0 = 0.f, a1 = 0.f;
    int i = start;
    for (; i + 2 <= end; i += 2) {
        int c0 = g_scol[i];
        int c1 = g_scol[i + 1];
        float v0 = g_sval[i];
        float v1 = g_sval[i + 1];
        const float* s0 = g_g + (size_t)c0 * OUT_DIM;
        const float* s1 = g_g + (size_t)c1 * OUT_DIM;
        float x0 = s0[lane], x1 = s1[lane];
        float y0 = hi ? s0[32 + lane] : 0.f;
        float y1 = hi ? s1[32 + lane] : 0.f;
        a0 = fmaf(v0, x0, a0); a0 = fmaf(v1, x1, a0);
        a1 = fmaf(v0, y0, a1); a1 = fmaf(v1, y1, a1);
    }
    if (i < end) {
        int c0 = g_scol[i];
        float v0 = g_sval[i];
        const float* s0 = g_g + (size_t)c0 * OUT_DIM;
        a0 = fmaf(v0, s0[lane], a0);
        if (hi) a1 = fmaf(v0, s0[32 + lane], a1);
    }

    float o0 = a0 + b2[lane];
    float o1 = hi ? (a1 + b2[32 + lane]) : -1e30f;

    float m = fmaxf(o0, o1);
#pragma unroll
    for (int off = 16; off > 0; off >>= 1)
        m = fmaxf(m, __shfl_xor_sync(0xFFFFFFFF, m, off));

    float s = __expf(o0 - m) + (hi ? __expf(o1 - m) : 0.f);
#pragma unroll
    for (int off = 16; off > 0; off >>= 1)
        s += __shfl_xor_sync(0xFFFFFFFF, s, off);

    float lse = __logf(s) + m;
    float* dst = out + (size_t)row * OUT_DIM;
    dst[lane] = o0 - lse;
    if (hi) dst[32 + lane] = o1 - lse;
}

// ---------------------------------------------------------------------------
extern "C" void kernel_launch(void* const* d_in, const int* in_sizes, int n_in,
                              void* d_out, int out_size) {
    const float* x  = (const float*)d_in[0];
    const int*   er = (const int*)  d_in[1];
    const int*   ec = (const int*)  d_in[2];
    const float* ev = (const float*)d_in[3];
    const float* W1 = (const float*)d_in[4];
    const float* b1 = (const float*)d_in[5];
    const float* W2 = (const float*)d_in[6];
    const float* b2 = (const float*)d_in[7];
    float* out = (float*)d_out;

    (void)in_sizes; (void)n_in; (void)out_size;

    // CSR build (counting sort by dest row; also permutes (col,val))
    csr_zero_kernel<<<(N_NODES + 255) / 256, 256>>>();
    csr_count_kernel<<<(N_EDGES + 255) / 256, 256>>>(er);
    csr_scan_kernel<<<1, 1024>>>();
    csr_scatter_kernel<<<(N_EDGES + 255) / 256, 256>>>(er, ec, ev);

    // y = x @ W1
    gemm1_kernel<<<(N_NODES + 127) / 128, 256>>>(x, W1);

    // h = relu(A @ y + b1)   (gather, no atomics)
    spmm1_gather_kernel<<<N_NODES / 8, 256>>>(b1);

    // g = h @ W2
    gemm2_kernel<<<N_NODES / 32, dim3(20, 8)>>>(W2);

    // out = log_softmax(A @ g + b2)   (gather + fused softmax)
    spmm2_softmax_kernel<<<N_NODES / 8, 256>>>(b2, out);
}

// round 12
// speedup vs baseline: 1.6523x; 1.0888x over previous
#include <cuda_runtime.h>
#include <math.h>

#define N_NODES 40000
#define N_EDGES 640000
#define IN_DIM  512
#define HID_DIM 128
#define OUT_DIM 40

typedef unsigned long long u64;

// packed fp32x2 FMA: d = a*b + d  (two independent fp32 FMAs, one instruction)
#define FMA_F32X2(d, a, b) \
    asm("fma.rn.f32x2 %0, %1, %2, %0;" : "+l"(d) : "l"(a), "l"(b))

#define PACK_BOTH(d, s) \
    asm("mov.b64 %0, {%1, %1};" : "=l"(d) : "f"(s))

#define UNPACK2(lo, hi, d) \
    asm("mov.b64 {%0, %1}, %2;" : "=f"(lo), "=f"(hi) : "l"(d))

// ---------------------------------------------------------------------------
// Scratch (__device__ globals; allocation-free rule)
// ---------------------------------------------------------------------------
__device__ float g_y[(size_t)N_NODES * HID_DIM];   // x @ W1
__device__ float g_h[(size_t)N_NODES * HID_DIM];   // relu(spmm1 + b1)
__device__ float g_g[(size_t)N_NODES * OUT_DIM];   // g_h @ W2
__device__ int   g_cnt[N_NODES];                   // histogram / running offsets
__device__ int   g_rowptr[N_NODES + 1];            // CSR row pointers
__device__ int   g_scol[N_EDGES];                  // edge cols sorted by row
__device__ float g_sval[N_EDGES];                  // edge vals sorted by row

// ---------------------------------------------------------------------------
// CSR build: zero -> count -> scan -> scatter
// ---------------------------------------------------------------------------
__global__ __launch_bounds__(256) void csr_zero_kernel() {
    int i = blockIdx.x * blockDim.x + threadIdx.x;
    if (i < N_NODES) g_cnt[i] = 0;
}

__global__ __launch_bounds__(256) void csr_count_kernel(const int* __restrict__ erow) {
    int e = blockIdx.x * blockDim.x + threadIdx.x;
    if (e < N_EDGES) atomicAdd(&g_cnt[erow[e]], 1);
}

// single-block exclusive scan over g_cnt -> g_rowptr (and g_cnt = running offsets)
__global__ __launch_bounds__(1024) void csr_scan_kernel() {
    __shared__ int warp_sums[32];
    __shared__ int s_carry;
    const int tid = threadIdx.x;
    const int lane = tid & 31;
    const int wid = tid >> 5;
    if (tid == 0) s_carry = 0;
    __syncthreads();

    for (int base = 0; base < ((N_NODES + 1024) / 1024) * 1024; base += 1024) {
        int idx = base + tid;
        int v = (idx < N_NODES) ? g_cnt[idx] : 0;
        int x = v;
#pragma unroll
        for (int o = 1; o < 32; o <<= 1) {
            int t = __shfl_up_sync(0xFFFFFFFF, x, o);
            if (lane >= o) x += t;
        }
        if (lane == 31) warp_sums[wid] = x;
        __syncthreads();
        if (wid == 0) {
            int w = warp_sums[lane];
#pragma unroll
            for (int o = 1; o < 32; o <<= 1) {
                int t = __shfl_up_sync(0xFFFFFFFF, w, o);
                if (lane >= o) w += t;
            }
            warp_sums[lane] = w;
        }
        __syncthreads();
        int carry = s_carry;
        int excl = x - v + (wid > 0 ? warp_sums[wid - 1] : 0) + carry;
        if (idx <= N_NODES) {
            g_rowptr[idx] = excl;
            if (idx < N_NODES) g_cnt[idx] = excl;
        }
        __syncthreads();
        if (tid == 0) s_carry = carry + warp_sums[31];
        __syncthreads();
    }
}

__global__ __launch_bounds__(256) void csr_scatter_kernel(const int* __restrict__ erow,
                                                          const int* __restrict__ ecol,
                                                          const float* __restrict__ eval) {
    int e = blockIdx.x * blockDim.x + threadIdx.x;
    if (e >= N_EDGES) return;
    int r = erow[e];
    int pos = atomicAdd(&g_cnt[r], 1);
    g_scol[pos] = ecol[e];
    g_sval[pos] = eval[e];
}

// ---------------------------------------------------------------------------
// GEMM1: Y[M,128] = X[M,512] @ W1[512,128]
// fp32, 128x128x8 tile, 8 rows x 4 col-pairs per thread, f32x2 packed FMA
// ---------------------------------------------------------------------------
__global__ __launch_bounds__(256) void gemm1_kernel(const float* __restrict__ A,
                                                    const float* __restrict__ W) {
    __shared__ __align__(16) float As[8][132];   // [k][m], padded
    __shared__ __align__(16) float Bs[8][128];   // [k][n]

    const int tid = threadIdx.x;
    const int block_row = blockIdx.x * 128;
    const int tx = tid & 15;    // n-tile (8 cols = 4 pairs)
    const int ty = tid >> 4;    // m-tile (8 rows)

    u64 accp[8][4];
#pragma unroll
    for (int i = 0; i < 8; i++)
#pragma unroll
        for (int j = 0; j < 4; j++) accp[i][j] = 0ULL;

    const int a_row = tid >> 1;
    const int a_col = (tid & 1) * 4;
    const int b_row = tid >> 5;
    const int b_col = (tid & 31) * 4;

    const int gr = block_row + a_row;
    const bool a_ok = (gr < N_NODES);
    const float* Aptr = A + (size_t)(a_ok ? gr : 0) * IN_DIM + a_col;

    for (int k0 = 0; k0 < IN_DIM; k0 += 8) {
        float4 av = a_ok ? *(const float4*)(Aptr + k0) : make_float4(0.f, 0.f, 0.f, 0.f);
        float4 bv = *(const float4*)(W + (size_t)(k0 + b_row) * HID_DIM + b_col);
        As[a_col + 0][a_row] = av.x;
        As[a_col + 1][a_row] = av.y;
        As[a_col + 2][a_row] = av.z;
        As[a_col + 3][a_row] = av.w;
        *(float4*)&Bs[b_row][b_col] = bv;
        __syncthreads();
#pragma unroll
        for (int k = 0; k < 8; k++) {
            u64 ap[8], bp[4];
#pragma unroll
            for (int i = 0; i < 8; i++) {
                float a = As[k][ty * 8 + i];
                PACK_BOTH(ap[i], a);
            }
#pragma unroll
            for (int j = 0; j < 4; j++)
                bp[j] = *(const u64*)&Bs[k][tx * 8 + j * 2];   // LDS.64, 8B-aligned
#pragma unroll
            for (int i = 0; i < 8; i++)
#pragma unroll
                for (int j = 0; j < 4; j++)
                    FMA_F32X2(accp[i][j], ap[i], bp[j]);
        }
        __syncthreads();
    }

#pragma unroll
    for (int i = 0; i < 8; i++) {
        int r = block_row + ty * 8 + i;
        if (r < N_NODES) {
            float o[8];
#pragma unroll
            for (int j = 0; j < 4; j++) UNPACK2(o[2 * j], o[2 * j + 1], accp[i][j]);
            *(float4*)(g_y + (size_t)r * HID_DIM + tx * 8 + 0) = make_float4(o[0], o[1], o[2], o[3]);
            *(float4*)(g_y + (size_t)r * HID_DIM + tx * 8 + 4) = make_float4(o[4], o[5], o[6], o[7]);
        }
    }
}

// ---------------------------------------------------------------------------
// SpMM1 gather: g_h[row] = relu( sum_e val*g_y[col] + b1 )   (warp per row)
// 4-edge unroll for MLP
// ---------------------------------------------------------------------------
__global__ __launch_bounds__(256) void spmm1_gather_kernel(const float* __restrict__ b1) {
    const int row = blockIdx.x * 8 + (threadIdx.x >> 5);
    const int lane = threadIdx.x & 31;
    const int start = g_rowptr[row];
    const int end = g_rowptr[row + 1];

    float4 acc = make_float4(0.f, 0.f, 0.f, 0.f);
    int i = start;
    for (; i + 4 <= end; i += 4) {
        int c0 = g_scol[i];
        int c1 = g_scol[i + 1];
        int c2 = g_scol[i + 2];
        int c3 = g_scol[i + 3];
        float v0 = g_sval[i];
        float v1 = g_sval[i + 1];
        float v2 = g_sval[i + 2];
        float v3 = g_sval[i + 3];
        float4 m0 = *(const float4*)(g_y + (size_t)c0 * HID_DIM + lane * 4);
        float4 m1 = *(const float4*)(g_y + (size_t)c1 * HID_DIM + lane * 4);
        float4 m2 = *(const float4*)(g_y + (size_t)c2 * HID_DIM + lane * 4);
        float4 m3 = *(const float4*)(g_y + (size_t)c3 * HID_DIM + lane * 4);
        acc.x = fmaf(v0, m0.x, acc.x); acc.y = fmaf(v0, m0.y, acc.y);
        acc.z = fmaf(v0, m0.z, acc.z); acc.w = fmaf(v0, m0.w, acc.w);
        acc.x = fmaf(v1, m1.x, acc.x); acc.y = fmaf(v1, m1.y, acc.y);
        acc.z = fmaf(v1, m1.z, acc.z); acc.w = fmaf(v1, m1.w, acc.w);
        acc.x = fmaf(v2, m2.x, acc.x); acc.y = fmaf(v2, m2.y, acc.y);
        acc.z = fmaf(v2, m2.z, acc.z); acc.w = fmaf(v2, m2.w, acc.w);
        acc.x = fmaf(v3, m3.x, acc.x); acc.y = fmaf(v3, m3.y, acc.y);
        acc.z = fmaf(v3, m3.z, acc.z); acc.w = fmaf(v3, m3.w, acc.w);
    }
    for (; i < end; i++) {
        int c0 = g_scol[i];
        float v0 = g_sval[i];
        float4 m0 = *(const float4*)(g_y + (size_t)c0 * HID_DIM + lane * 4);
        acc.x = fmaf(v0, m0.x, acc.x); acc.y = fmaf(v0, m0.y, acc.y);
        acc.z = fmaf(v0, m0.z, acc.z); acc.w = fmaf(v0, m0.w, acc.w);
    }

    float4 b = *(const float4*)(b1 + lane * 4);
    float4 r;
    r.x = fmaxf(acc.x + b.x, 0.f);
    r.y = fmaxf(acc.y + b.y, 0.f);
    r.z = fmaxf(acc.z + b.z, 0.f);
    r.w = fmaxf(acc.w + b.w, 0.f);
    *(float4*)(g_h + (size_t)row * HID_DIM + lane * 4) = r;
}

// ---------------------------------------------------------------------------
// GEMM2: g_g[32 rows x 40 cols per block] = g_h @ W2
// thread tile 4 rows x 1 col-pair (f32x2); block (20,8) = 160 threads
// ---------------------------------------------------------------------------
__global__ __launch_bounds__(160) void gemm2_kernel(const float* __restrict__ W2) {
    __shared__ __align__(16) float hs[32][132];
    __shared__ __align__(16) float W2s[HID_DIM][OUT_DIM];

    const int tid = threadIdx.y * 20 + threadIdx.x;
    const int tx = threadIdx.x;   // 0..19  (col pair)
    const int ty = threadIdx.y;   // 0..7   (row quad)
    const int row0 = blockIdx.x * 32;

    for (int i = tid; i < HID_DIM * OUT_DIM; i += 160)
        ((float*)W2s)[i] = W2[i];

    for (int i = tid; i < 32 * (HID_DIM / 4); i += 160) {
        int rr = i >> 5;
        int c4 = i & 31;
        float4 v = *(const float4*)(g_h + (size_t)(row0 + rr) * HID_DIM + c4 * 4);
        *(float4*)&hs[rr][c4 * 4] = v;
    }
    __syncthreads();

    u64 accp[4];
#pragma unroll
    for (int i = 0; i < 4; i++) accp[i] = 0ULL;

#pragma unroll 4
    for (int k = 0; k < HID_DIM; k++) {
        u64 wp = *(const u64*)&W2s[k][tx * 2];   // 8B-aligned (tx*2 even, 40 even)
        u64 hp[4];
#pragma unroll
        for (int i = 0; i < 4; i++) {
            float h = hs[ty * 4 + i][k];
            PACK_BOTH(hp[i], h);
        }
#pragma unroll
        for (int i = 0; i < 4; i++) FMA_F32X2(accp[i], hp[i], wp);
    }

#pragma unroll
    for (int i = 0; i < 4; i++) {
        int r = row0 + ty * 4 + i;
        float lo, hi;
        UNPACK2(lo, hi, accp[i]);
        *(float2*)(g_g + (size_t)r * OUT_DIM + tx * 2) = make_float2(lo, hi);
    }
}

// ---------------------------------------------------------------------------
// SpMM2 + bias + log_softmax fused: warp per row
// ---------------------------------------------------------------------------
__global__ __launch_bounds__(256) void spmm2_softmax_kernel(const float* __restrict__ b2,
                                                            float* __restrict__ out) {
    const int row = blockIdx.x * 8 + (threadIdx.x >> 5);
    const int lane = threadIdx.x & 31;
    const int start = g_rowptr[row];
    const int end = g_rowptr[row + 1];
    const bool hi = lane < (OUT_DIM - 32);

    float a0 = 0.f, a1 = 0.f;
    int i = start;
    for (; i + 2 <= end; i += 2) {
        int c0 = g_scol[i];
        int c1 = g_scol[i + 1];
        float v0 = g_sval[i];
        float v1 = g_sval[i + 1];
        const float* s0 = g_g + (size_t)c0 * OUT_DIM;
        const float* s1 = g_g + (size_t)c1 * OUT_DIM;
        float x0 = s0[lane], x1 = s1[lane];
        float y0 = hi ? s0[32 + lane] : 0.f;
        float y1 = hi ? s1[32 + lane] : 0.f;
        a0 = fmaf(v0, x0, a0); a0 = fmaf(v1, x1, a0);
        a1 = fmaf(v0, y0, a1); a1 = fmaf(v1, y1, a1);
    }
    if (i < end) {
        int c0 = g_scol[i];
        float v0 = g_sval[i];
        const float* s0 = g_g + (size_t)c0 * OUT_DIM;
        a0 = fmaf(v0, s0[lane], a0);
        if (hi) a1 = fmaf(v0, s0[32 + lane], a1);
    }

    float o0 = a0 + b2[lane];
    float o1 = hi ? (a1 + b2[32 + lane]) : -1e30f;

    float m = fmaxf(o0, o1);
#pragma unroll
    for (int off = 16; off > 0; off >>= 1)
        m = fmaxf(m, __shfl_xor_sync(0xFFFFFFFF, m, off));

    float s = __expf(o0 - m) + (hi ? __expf(o1 - m) : 0.f);
#pragma unroll
    for (int off = 16; off > 0; off >>= 1)
        s += __shfl_xor_sync(0xFFFFFFFF, s, off);

    float lse = __logf(s) + m;
    float* dst = out + (size_t)row * OUT_DIM;
    dst[lane] = o0 - lse;
    if (hi) dst[32 + lane] = o1 - lse;
}

// ---------------------------------------------------------------------------
extern "C" void kernel_launch(void* const* d_in, const int* in_sizes, int n_in,
                              void* d_out, int out_size) {
    const float* x  = (const float*)d_in[0];
    const int*   er = (const int*)  d_in[1];
    const int*   ec = (const int*)  d_in[2];
    const float* ev = (const float*)d_in[3];
    const float* W1 = (const float*)d_in[4];
    const float* b1 = (const float*)d_in[5];
    const float* W2 = (const float*)d_in[6];
    const float* b2 = (const float*)d_in[7];
    float* out = (float*)d_out;

    (void)in_sizes; (void)n_in; (void)out_size;

    // CSR build (counting sort by dest row; also permutes (col,val))
    csr_zero_kernel<<<(N_NODES + 255) / 256, 256>>>();
    csr_count_kernel<<<(N_EDGES + 255) / 256, 256>>>(er);
    csr_scan_kernel<<<1, 1024>>>();
    csr_scatter_kernel<<<(N_EDGES + 255) / 256, 256>>>(er, ec, ev);

    // y = x @ W1   (f32x2 packed FMA)
    gemm1_kernel<<<(N_NODES + 127) / 128, 256>>>(x, W1);

    // h = relu(A @ y + b1)
    spmm1_gather_kernel<<<N_NODES / 8, 256>>>(b1);

    // g = h @ W2   (f32x2 packed FMA)
    gemm2_kernel<<<N_NODES / 32, dim3(20, 8)>>>(W2);

    // out = log_softmax(A @ g + b2)
    spmm2_softmax_kernel<<<N_NODES / 8, 256>>>(b2, out);
}